// round 1
// baseline (speedup 1.0000x reference)
#include <cuda_runtime.h>

#define B_ 512
#define S_ 512
#define T_ 128
#define NEGV (-10000.0f)
#define START_ID 0
#define END_ID 1

__device__ float g_diff[B_];

// packed f32x2 helpers
__device__ __forceinline__ unsigned long long pack2(float lo, float hi) {
    unsigned long long r;
    asm("mov.b64 %0, {%1, %2};" : "=l"(r) : "r"(__float_as_uint(lo)), "r"(__float_as_uint(hi)));
    return r;
}
__device__ __forceinline__ float hsum2(unsigned long long v) {
    unsigned int lo, hi;
    asm("mov.b64 {%0, %1}, %2;" : "=r"(lo), "=r"(hi) : "l"(v));
    return __uint_as_float(lo) + __uint_as_float(hi);
}
#define FMA2(acc, e, a) asm("fma.rn.f32x2 %0, %1, %2, %0;" : "+l"(acc) : "l"(e), "l"(a))
#define ADD2(o, a, b)   asm("add.rn.f32x2 %0, %1, %2;" : "=l"(o) : "l"(a), "l"(b))

__device__ __forceinline__ float warp_sum(float v) {
#pragma unroll
    for (int o = 16; o; o >>= 1) v += __shfl_xor_sync(0xffffffffu, v, o);
    return v;
}
__device__ __forceinline__ float warp_max(float v) {
#pragma unroll
    for (int o = 16; o; o >>= 1) v = fmaxf(v, __shfl_xor_sync(0xffffffffu, v, o));
    return v;
}

__global__ void __launch_bounds__(T_, 2) crf_kernel(
    const float* __restrict__ x,      // [B,S,T]
    const int*   __restrict__ tags,   // [B,S]
    const float* __restrict__ mask,   // [B,S]
    const float* __restrict__ trans)  // [T,T]
{
    const int b = blockIdx.x;
    const int i = threadIdx.x;
    const int lane = i & 31, w = i >> 5;

    __shared__ __align__(16) float sa[2][T_];
    __shared__ float s_m[2];
    __shared__ float s_red[4];
    __shared__ int   s_len;

    // ---- sequence length = sum(mask[b,:]) (mask is a contiguous prefix) ----
    float lm = 0.f;
#pragma unroll
    for (int t = i; t < S_; t += T_) lm += mask[b * S_ + t];
    lm = warp_sum(lm);
    if (lane == 0) s_red[w] = lm;
    __syncthreads();
    if (i == 0) s_len = (int)(s_red[0] + s_red[1] + s_red[2] + s_red[3] + 0.5f);

    // ---- thread i keeps exp(trans[i,:]) as 64 packed f32x2 registers ----
    unsigned long long er[T_ / 2];
    {
        const float4* tr4 = reinterpret_cast<const float4*>(trans + i * T_);
#pragma unroll
        for (int j = 0; j < T_ / 4; j++) {
            float4 v = __ldg(tr4 + j);
            er[2 * j]     = pack2(expf(v.x), expf(v.y));
            er[2 * j + 1] = pack2(expf(v.z), expf(v.w));
        }
    }
    __syncthreads();
    const int len = s_len;

    // ---- forward recurrence ----
    float alpha = (i == START_ID) ? 0.f : NEGV;
    float m = 0.f;                         // = alpha[0]; safe renorm (spread bounded)
    const float* xb = x + (size_t)b * S_ * T_;
    float xt = xb[i];                      // prefetch t=0
    int p = 0;
    for (int t = 0; t < len; t++) {
        sa[p][i] = expf(alpha - m);
        __syncthreads();
        float xnext = (t + 1 < len) ? xb[(size_t)(t + 1) * T_ + i] : 0.f;

        const unsigned long long* sap =
            reinterpret_cast<const unsigned long long*>(sa[p]);
        unsigned long long a0 = 0ull, a1 = 0ull, a2 = 0ull, a3 = 0ull;
#pragma unroll
        for (int j = 0; j < T_ / 2; j += 4) {
            FMA2(a0, er[j],     sap[j]);
            FMA2(a1, er[j + 1], sap[j + 1]);
            FMA2(a2, er[j + 2], sap[j + 2]);
            FMA2(a3, er[j + 3], sap[j + 3]);
        }
        unsigned long long s01, s23, s;
        ADD2(s01, a0, a1); ADD2(s23, a2, a3); ADD2(s, s01, s23);

        alpha = xt + m + logf(hsum2(s));
        if (i == 0) s_m[p] = alpha;
        __syncthreads();
        m = s_m[p];
        p ^= 1;
        xt = xnext;
    }

    // ---- fwd = logsumexp_i(alpha_i + trans[END, i]) ----
    float v = alpha + __ldg(trans + END_ID * T_ + i);
    float mx = warp_max(v);
    __syncthreads();
    if (lane == 0) s_red[w] = mx;
    __syncthreads();
    mx = fmaxf(fmaxf(s_red[0], s_red[1]), fmaxf(s_red[2], s_red[3]));
    float e = expf(v - mx);
    float se = warp_sum(e);
    __syncthreads();
    if (lane == 0) s_red[w] = se;
    __syncthreads();
    float fwd = mx + logf(s_red[0] + s_red[1] + s_red[2] + s_red[3]);

    // ---- gold path score ----
    const int* tb = tags + b * S_;
    float gs = 0.f;
    for (int u = i; u < len; u += T_) {
        int tn = tb[u + 1];
        int tc = tb[u];
        gs += xb[(size_t)u * T_ + tn] + __ldg(trans + tn * T_ + tc);
    }
    gs = warp_sum(gs);
    __syncthreads();
    if (lane == 0) s_red[w] = gs;
    __syncthreads();
    if (i == 0) {
        float gtot = s_red[0] + s_red[1] + s_red[2] + s_red[3];
        gtot += __ldg(trans + END_ID * T_ + tb[len]);
        g_diff[b] = fwd - gtot;
    }
}

// deterministic final mean over batch
__global__ void finalize_kernel(float* out) {
    __shared__ float sh[B_];
    int i = threadIdx.x;
    sh[i] = g_diff[i];
    __syncthreads();
#pragma unroll
    for (int s = B_ / 2; s > 0; s >>= 1) {
        if (i < s) sh[i] += sh[i + s];
        __syncthreads();
    }
    if (i == 0) out[0] = sh[0] * (1.0f / B_);
}

extern "C" void kernel_launch(void* const* d_in, const int* in_sizes, int n_in,
                              void* d_out, int out_size) {
    const float* x     = (const float*)d_in[0];
    const int*   tags  = (const int*)d_in[1];
    const float* mask  = (const float*)d_in[2];
    const float* trans = (const float*)d_in[3];
    crf_kernel<<<B_, T_>>>(x, tags, mask, trans);
    finalize_kernel<<<1, B_>>>((float*)d_out);
}